// round 5
// baseline (speedup 1.0000x reference)
#include <cuda_runtime.h>
#include <cuda_bf16.h>
#include <stdint.h>

// Problem constants (fixed by the dataset)
#define NN 100000
#define CC 64
#define EE 1200000
#define GG 256
#define EPS 1e-5f

// ---------------------------------------------------------------------------
// Scratch (device globals; no cudaMalloc allowed). 16B-aligned: these are
// accessed via float4 loads/stores and red.global.add.v4.f32.
// ---------------------------------------------------------------------------
__device__ __align__(16) float g_agg[NN * CC];     // neighbor-sum accumulator
__device__ __align__(16) float g_deg[NN];          // in-degree
__device__ __align__(16) float g_h[NN * CC];       // SAGE output
__device__ __align__(16) float g_tact[NN * 8];     // relu(x @ a1^T + a1_b)
__device__ __align__(16) float g_mean[GG * CC];    // per-graph mean
__device__ __align__(16) float g_rstd[GG * CC];    // per-graph rsqrt(var+eps)

// ---------------------------------------------------------------------------
// K0: zero agg + deg
// ---------------------------------------------------------------------------
__global__ void k0_zero(int n4, int n)
{
    int i = blockIdx.x * blockDim.x + threadIdx.x;
    if (i < n4) reinterpret_cast<float4*>(g_agg)[i] = make_float4(0.f, 0.f, 0.f, 0.f);
    if (i < n)  g_deg[i] = 0.f;
}

// ---------------------------------------------------------------------------
// K1: edge scatter. 4 threads per edge, each handles 4 float4 chunks.
// red.global.add.v4.f32: vector reduction (sm_90+), no return value.
// edge_index is int32 (JAX with x64 disabled downgrades int64 -> int32).
// ---------------------------------------------------------------------------
__device__ __forceinline__ void red_add_v4(float* addr, float4 v)
{
    asm volatile("red.global.add.v4.f32 [%0], {%1, %2, %3, %4};"
                 :: "l"(addr), "f"(v.x), "f"(v.y), "f"(v.z), "f"(v.w)
                 : "memory");
}

__global__ void k1_edges(const float* __restrict__ x,
                         const int* __restrict__ ei, int E)
{
    int i = blockIdx.x * blockDim.x + threadIdx.x;
    if (i >= 4 * E) return;
    int e = i >> 2;
    int q = i & 3;
    int s = ei[e];
    int d = ei[E + e];
    const float4* xs = reinterpret_cast<const float4*>(x) + (size_t)s * 16 + q * 4;
    float*        ad = g_agg + (size_t)d * 64 + q * 16;
#pragma unroll
    for (int c = 0; c < 4; c++) {
        float4 v = __ldg(xs + c);
        red_add_v4(ad + c * 4, v);
    }
    if (q == 0) atomicAdd(&g_deg[d], 1.0f);
}

// ---------------------------------------------------------------------------
// K2: per-node fused GEMM:
//   h = (agg/max(deg,1)) @ Wl^T + bl + x @ Wr^T        -> g_h
//   tact = relu(x @ a1_w^T + a1_b)                      -> g_tact
// Thread-per-node; 64 fp32 accumulators; weights in shared, transposed,
// read as uniform (broadcast) LDS.128.
// ---------------------------------------------------------------------------
__device__ __forceinline__ float f4get(const float4& v, int u)
{
    switch (u) { case 0: return v.x; case 1: return v.y; case 2: return v.z; default: return v.w; }
}

__global__ __launch_bounds__(256) void k2_node_gemm(
    const float* __restrict__ x,
    const float* __restrict__ Wl, const float* __restrict__ bl,
    const float* __restrict__ Wr,
    const float* __restrict__ a1w, const float* __restrict__ a1b, int N)
{
    __shared__ __align__(16) float sWl[64][64];  // [k][j] = Wl[j][k]
    __shared__ __align__(16) float sWr[64][64];  // [k][j] = Wr[j][k]
    __shared__ __align__(16) float sA1[64][8];   // [k][r] = a1w[r][k]
    __shared__ float sBl[64];

    for (int i = threadIdx.x; i < 4096; i += 256) {
        int j = i & 63, k = i >> 6;
        sWl[k][j] = Wl[j * 64 + k];
        sWr[k][j] = Wr[j * 64 + k];
    }
    for (int i = threadIdx.x; i < 512; i += 256) {
        int r = i & 7, k = i >> 3;
        sA1[k][r] = a1w[r * 64 + k];
    }
    if (threadIdx.x < 64) sBl[threadIdx.x] = bl[threadIdx.x];
    __syncthreads();

    int n = blockIdx.x * 256 + threadIdx.x;
    if (n >= N) return;

    float acc[64];
#pragma unroll
    for (int j = 0; j < 64; j++) acc[j] = sBl[j];
    float t[8];
#pragma unroll
    for (int r = 0; r < 8; r++) t[r] = __ldg(a1b + r);

    float inv = 1.0f / fmaxf(g_deg[n], 1.0f);
    const float4* xr = reinterpret_cast<const float4*>(x) + (size_t)n * 16;
    const float4* ar = reinterpret_cast<const float4*>(g_agg) + (size_t)n * 16;

#pragma unroll 1
    for (int k4 = 0; k4 < 16; k4++) {
        float4 xv = __ldg(xr + k4);
        float4 av = ar[k4];
        float ax[4] = { av.x * inv, av.y * inv, av.z * inv, av.w * inv };
        float xx[4] = { xv.x, xv.y, xv.z, xv.w };
#pragma unroll
        for (int kk = 0; kk < 4; kk++) {
            int k = k4 * 4 + kk;
            float ak = ax[kk], xk = xx[kk];
            const float4* wl4 = reinterpret_cast<const float4*>(&sWl[k][0]);
            const float4* wr4 = reinterpret_cast<const float4*>(&sWr[k][0]);
#pragma unroll
            for (int j4 = 0; j4 < 16; j4++) {
                float4 wl = wl4[j4];
                float4 wr = wr4[j4];
                acc[j4 * 4 + 0] = fmaf(ak, wl.x, fmaf(xk, wr.x, acc[j4 * 4 + 0]));
                acc[j4 * 4 + 1] = fmaf(ak, wl.y, fmaf(xk, wr.y, acc[j4 * 4 + 1]));
                acc[j4 * 4 + 2] = fmaf(ak, wl.z, fmaf(xk, wr.z, acc[j4 * 4 + 2]));
                acc[j4 * 4 + 3] = fmaf(ak, wl.w, fmaf(xk, wr.w, acc[j4 * 4 + 3]));
            }
            const float4* a14 = reinterpret_cast<const float4*>(&sA1[k][0]);
            float4 p = a14[0], q = a14[1];
            t[0] = fmaf(xk, p.x, t[0]); t[1] = fmaf(xk, p.y, t[1]);
            t[2] = fmaf(xk, p.z, t[2]); t[3] = fmaf(xk, p.w, t[3]);
            t[4] = fmaf(xk, q.x, t[4]); t[5] = fmaf(xk, q.y, t[5]);
            t[6] = fmaf(xk, q.z, t[6]); t[7] = fmaf(xk, q.w, t[7]);
        }
    }

    float4* hr = reinterpret_cast<float4*>(g_h) + (size_t)n * 16;
#pragma unroll
    for (int j4 = 0; j4 < 16; j4++)
        hr[j4] = make_float4(acc[j4 * 4 + 0], acc[j4 * 4 + 1], acc[j4 * 4 + 2], acc[j4 * 4 + 3]);

    float4* tr = reinterpret_cast<float4*>(g_tact) + (size_t)n * 2;
    tr[0] = make_float4(fmaxf(t[0], 0.f), fmaxf(t[1], 0.f), fmaxf(t[2], 0.f), fmaxf(t[3], 0.f));
    tr[1] = make_float4(fmaxf(t[4], 0.f), fmaxf(t[5], 0.f), fmaxf(t[6], 0.f), fmaxf(t[7], 0.f));
}

// ---------------------------------------------------------------------------
// K2b: per-graph stats. One block per graph; batch is SORTED (int32), so
// binary-search the segment boundaries. Single pass:
// var(out) = E[h^2] - (2a - a^2)*mean^2.
// ---------------------------------------------------------------------------
__global__ __launch_bounds__(256) void k2b_stats(
    const int* __restrict__ batch,
    const float* __restrict__ gn_alpha, int N)
{
    int g = blockIdx.x;
    int c = threadIdx.x & 63;
    int r = threadIdx.x >> 6;   // 0..3

    // lower_bound(batch, g)
    int lo = 0, hi = N;
    while (lo < hi) { int mid = (lo + hi) >> 1; if (batch[mid] < g) lo = mid + 1; else hi = mid; }
    int start = lo;
    lo = start; hi = N;
    while (lo < hi) { int mid = (lo + hi) >> 1; if (batch[mid] < g + 1) lo = mid + 1; else hi = mid; }
    int end = lo;

    float s0 = 0.f, q0 = 0.f, s1 = 0.f, q1 = 0.f;
    int i = start + r;
    for (; i + 4 < end; i += 8) {
        float v0 = g_h[(size_t)i * 64 + c];
        float v1 = g_h[(size_t)(i + 4) * 64 + c];
        s0 += v0; q0 = fmaf(v0, v0, q0);
        s1 += v1; q1 = fmaf(v1, v1, q1);
    }
    for (; i < end; i += 4) {
        float v0 = g_h[(size_t)i * 64 + c];
        s0 += v0; q0 = fmaf(v0, v0, q0);
    }
    float s = s0 + s1, q = q0 + q1;

    __shared__ float ss[4][64], sq[4][64];
    ss[r][c] = s; sq[r][c] = q;
    __syncthreads();
    if (r == 0) {
        s = ss[0][c] + ss[1][c] + ss[2][c] + ss[3][c];
        q = sq[0][c] + sq[1][c] + sq[2][c] + sq[3][c];
        float cnt = fmaxf((float)(end - start), 1.0f);
        float mu = s / cnt;
        float al = gn_alpha[c];
        float var = q / cnt - (2.0f * al - al * al) * mu * mu;
        var = fmaxf(var, 0.0f);
        g_mean[g * 64 + c] = mu;
        g_rstd[g * 64 + c] = rsqrtf(var + EPS);
    }
}

// ---------------------------------------------------------------------------
// K3: finalize. thread per (node, 4-channel chunk).
//   y    = w*(h - mean*alpha)*rstd + b
//   gate = sigmoid(tact @ a2_w^T + a2_b)
//   out  = relu(y + gate*x)
// ---------------------------------------------------------------------------
__global__ __launch_bounds__(256) void k3_finalize(
    const float* __restrict__ x, const int* __restrict__ batch,
    const float* __restrict__ gnw, const float* __restrict__ gnb,
    const float* __restrict__ gna,
    const float* __restrict__ a2w, const float* __restrict__ a2b,
    float* __restrict__ out, int N)
{
    int i = blockIdx.x * blockDim.x + threadIdx.x;
    if (i >= N * 16) return;
    int n  = i >> 4;
    int c4 = i & 15;
    int g  = batch[n];

    float4 hv = reinterpret_cast<const float4*>(g_h)[(size_t)n * 16 + c4];
    float4 xv = reinterpret_cast<const float4*>(x)[(size_t)n * 16 + c4];
    float4 mu = reinterpret_cast<const float4*>(g_mean)[g * 16 + c4];
    float4 rs = reinterpret_cast<const float4*>(g_rstd)[g * 16 + c4];
    float4 al = __ldg(reinterpret_cast<const float4*>(gna) + c4);
    float4 w4 = __ldg(reinterpret_cast<const float4*>(gnw) + c4);
    float4 b4 = __ldg(reinterpret_cast<const float4*>(gnb) + c4);
    float4 t0 = reinterpret_cast<const float4*>(g_tact)[(size_t)n * 2];
    float4 t1 = reinterpret_cast<const float4*>(g_tact)[(size_t)n * 2 + 1];
    float4 b2 = __ldg(reinterpret_cast<const float4*>(a2b) + c4);

    float res[4];
#pragma unroll
    for (int u = 0; u < 4; u++) {
        int j = c4 * 4 + u;
        float4 wa = __ldg(reinterpret_cast<const float4*>(a2w) + j * 2);
        float4 wb = __ldg(reinterpret_cast<const float4*>(a2w) + j * 2 + 1);
        float z = wa.x * t0.x + wa.y * t0.y + wa.z * t0.z + wa.w * t0.w
                + wb.x * t1.x + wb.y * t1.y + wb.z * t1.z + wb.w * t1.w
                + f4get(b2, u);
        float gate = 1.0f / (1.0f + __expf(-z));
        float y = f4get(w4, u) * (f4get(hv, u) - f4get(mu, u) * f4get(al, u)) * f4get(rs, u)
                + f4get(b4, u);
        res[u] = fmaxf(y + gate * f4get(xv, u), 0.0f);
    }
    reinterpret_cast<float4*>(out)[(size_t)n * 16 + c4] =
        make_float4(res[0], res[1], res[2], res[3]);
}

// ---------------------------------------------------------------------------
// launch
// ---------------------------------------------------------------------------
extern "C" void kernel_launch(void* const* d_in, const int* in_sizes, int n_in,
                              void* d_out, int out_size)
{
    const float* x     = (const float*)d_in[0];
    const int*   ei    = (const int*)d_in[1];     // int32 (JAX x64 disabled)
    const int*   batch = (const int*)d_in[2];     // int32
    const float* Wl    = (const float*)d_in[3];
    const float* bl    = (const float*)d_in[4];
    const float* Wr    = (const float*)d_in[5];
    const float* gnw   = (const float*)d_in[6];
    const float* gnb   = (const float*)d_in[7];
    const float* gna   = (const float*)d_in[8];
    const float* a1w   = (const float*)d_in[9];
    const float* a1b   = (const float*)d_in[10];
    const float* a2w   = (const float*)d_in[11];
    const float* a2b   = (const float*)d_in[12];
    float*       out   = (float*)d_out;

    int N = in_sizes[0] / CC;          // 100000
    int E = in_sizes[1] / 2;           // 1200000

    // K0: zero agg + deg
    {
        int n4 = (N * CC) / 4;
        k0_zero<<<(n4 + 255) / 256, 256>>>(n4, N);
    }
    // K1: edge scatter
    {
        long long total = (long long)E * 4;
        k1_edges<<<(int)((total + 255) / 256), 256>>>(x, ei, E);
    }
    // K2: node GEMM + attention layer 1
    k2_node_gemm<<<(N + 255) / 256, 256>>>(x, Wl, bl, Wr, a1w, a1b, N);
    // K2b: per-graph stats
    k2b_stats<<<GG, 256>>>(batch, gna, N);
    // K3: finalize
    k3_finalize<<<(N * 16 + 255) / 256, 256>>>(x, batch, gnw, gnb, gna, a2w, a2b, out, N);
}